// round 11
// baseline (speedup 1.0000x reference)
#include <cuda_runtime.h>
#include <cuda_bf16.h>

// z:     [M=4096, P=2]  float32
// mu:    [B=8, N=2048, P=2] float32
// sigma: [B=8, N=2048, 1] float32
// out:   [B, N, M] float32 = exp(-d2 / (2*sig^2)), sig = clip(sigma, 0.1, 10)
//
// Two kernels:
//  1) param_kernel: per row, precompute {c, A, B, D} with
//     c = -log2(e)/(2 s^2), A = -2c*mu0, B = -2c*mu1, D = c*(mu0^2+mu1^2)
//     into a __device__ global float4 buffer (division/clip done ONCE per row,
//     not once per row per block).
//  2) rbf_kernel: persistent blocks, each owns a fixed half-row; z (zx,zy,zsq)
//     lives in registers forever. Hot loop per row: 1 prefetched LDG.128 of
//     params, 8 x (3 FFMA + 1 MUFU.EX2 via inline ptx), 2 streaming STG.128.

#define M_GRID  4096
#define THREADS 256
#define BLOCKS_PER_SM 5
#define M_PER_THREAD 8
#define MAX_ROWS 16384

__device__ float4 g_params[MAX_ROWS];

__global__ void param_kernel(const float* __restrict__ mu,
                             const float* __restrict__ sigma,
                             int rows)
{
    int row = blockIdx.x * blockDim.x + threadIdx.x;
    if (row >= rows) return;
    float mu0 = mu[row * 2 + 0];
    float mu1 = mu[row * 2 + 1];
    float s = fminf(fmaxf(sigma[row], 0.1f), 10.0f);
    float c = -1.44269504088896340736f / (2.0f * s * s);
    float4 p;
    p.x = c;
    p.y = -2.0f * c * mu0;                 // A
    p.z = -2.0f * c * mu1;                 // B
    p.w = c * (mu0 * mu0 + mu1 * mu1);     // D
    g_params[row] = p;
}

__device__ __forceinline__ float ex2_fast(float x) {
    float r;
    asm("ex2.approx.ftz.f32 %0, %1;" : "=f"(r) : "f"(x));
    return r;
}

__global__ void __launch_bounds__(THREADS, BLOCKS_PER_SM) rbf_kernel(
    const float* __restrict__ z,
    float* __restrict__ out,
    int rows)
{
    const int t    = threadIdx.x;
    const int half = blockIdx.x & 1;            // which 2048-wide half of the row
    const int rstart  = blockIdx.x >> 1;
    const int rstride = gridDim.x >> 1;

    const int m0 = half * (M_GRID / 2) + t * M_PER_THREAD;

    // Load z once into registers
    float zx[M_PER_THREAD], zy[M_PER_THREAD], zsq[M_PER_THREAD];
    {
        const float4* zv = reinterpret_cast<const float4*>(z + 2 * m0);
        #pragma unroll
        for (int i = 0; i < 4; i++) {
            float4 v = zv[i];
            zx[2*i]   = v.x; zy[2*i]   = v.y;
            zx[2*i+1] = v.z; zy[2*i+1] = v.w;
        }
        #pragma unroll
        for (int i = 0; i < M_PER_THREAD; i++)
            zsq[i] = zx[i] * zx[i] + zy[i] * zy[i];
    }

    // Prefetch first row's params (broadcast LDG.128, L2-resident)
    float4 p = __ldg(&g_params[rstart]);

    for (int row = rstart; row < rows; row += rstride) {
        const float4 cur = p;
        const int nrow = row + rstride;
        if (nrow < rows) p = __ldg(&g_params[nrow]);

        // arg_i = c*zsq + A*zx + B*zy + D   (3 FFMA), then 1 MUFU.EX2
        float r[M_PER_THREAD];
        #pragma unroll
        for (int i = 0; i < M_PER_THREAD; i++) {
            float e = fmaf(zy[i], cur.z, cur.w);
            e = fmaf(zx[i], cur.y, e);
            e = fmaf(zsq[i], cur.x, e);
            r[i] = ex2_fast(e);
        }

        float4* ov = reinterpret_cast<float4*>(out + (size_t)row * M_GRID + m0);
        __stcs(&ov[0], make_float4(r[0], r[1], r[2], r[3]));
        __stcs(&ov[1], make_float4(r[4], r[5], r[6], r[7]));
    }
}

extern "C" void kernel_launch(void* const* d_in, const int* in_sizes, int n_in,
                              void* d_out, int out_size)
{
    const float* z     = (const float*)d_in[0];  // [4096, 2]
    const float* mu    = (const float*)d_in[1];  // [8, 2048, 2]
    const float* sigma = (const float*)d_in[2];  // [8, 2048, 1]
    float* out = (float*)d_out;                  // [8, 2048, 4096]

    int rows = in_sizes[2];                      // B*N = 16384
    if (rows > MAX_ROWS) rows = MAX_ROWS;

    param_kernel<<<(rows + 255) / 256, 256>>>(mu, sigma, rows);

    int blocks = 148 * BLOCKS_PER_SM;            // 740 (even: half-row split)
    blocks &= ~1;
    rbf_kernel<<<blocks, THREADS>>>(z, out, rows);
}